// round 14
// baseline (speedup 1.0000x reference)
#include <cuda_runtime.h>
#include <math.h>
#include <stdint.h>

#define SQ      8192
#define NBATCH  2
#define S_TOT   21760
#define NQ      (NBATCH*SQ)      // 16384
#define NS      (NBATCH*S_TOT)   // 43520

// Fused phase-1 grid: 680 tf32-vmask CTAs + 256 logits CTAs + 512 deltas CTAs
#define N_VM   680
#define N_LG   256
#define N_DL   512
#define N_TOT  1448

// tf32 pipeline smem geometry
// A stage: [m][20] floats (stride-20 pad)                  = 10240 B
// B stage: [wn(2)][grp(8)][k(16)][nf(8)] grp stride 132 fl =  8448 B
#define A_STAGE_BYTES  (128*20*4)
#define B_STAGE_BYTES  (2*8*132*4)
#define STAGE_BYTES    (A_STAGE_BYTES + B_STAGE_BYTES)   // 18688
#define TF32_DSMEM     (3 * STAGE_BYTES)                 // 56064

// Scratch (device globals: no allocation allowed)
__device__ float g_vmask [(size_t)NS*256];
__device__ float g_logits[(size_t)NQ*128];
__device__ float g_deltas[(size_t)NQ*256];
__device__ float g_mdv   [(size_t)NQ*256];
__device__ float g_Wval_r[256*256];   // tf32-RNA rounded + fragment-permuted
__device__ float g_Wout_r[256*256];

// ===========================================================================
// PTX helpers
// ===========================================================================
__device__ __forceinline__ uint32_t f2tf32(float v) {
    uint32_t r;
    asm("cvt.rna.tf32.f32 %0, %1;" : "=r"(r) : "f"(v));
    return r;
}
__device__ __forceinline__ void mma_tf32(float c[4],
                                         uint32_t a0, uint32_t a1,
                                         uint32_t a2, uint32_t a3,
                                         uint32_t b0, uint32_t b1) {
    asm volatile(
        "mma.sync.aligned.m16n8k8.row.col.f32.tf32.tf32.f32 "
        "{%0,%1,%2,%3}, {%4,%5,%6,%7}, {%8,%9}, {%0,%1,%2,%3};"
        : "+f"(c[0]), "+f"(c[1]), "+f"(c[2]), "+f"(c[3])
        : "r"(a0), "r"(a1), "r"(a2), "r"(a3), "r"(b0), "r"(b1));
}
__device__ __forceinline__ uint32_t smem_u32(const void* p) {
    uint32_t a;
    asm("{ .reg .u64 t; cvta.to.shared.u64 t, %1; cvt.u32.u64 %0, t; }"
        : "=r"(a) : "l"(p));
    return a;
}
__device__ __forceinline__ void cp_async16(uint32_t dst, const void* src) {
    asm volatile("cp.async.cg.shared.global [%0], [%1], 16;"
                 :: "r"(dst), "l"(src));
}
#define CP_COMMIT() asm volatile("cp.async.commit_group;" ::: "memory")
#define CP_WAIT1()  asm volatile("cp.async.wait_group 1;" ::: "memory")

// ===========================================================================
// Pipelined tf32 GEMM body:
//   C[.. x Nc] = (A[.. x 256] @ W[256 x Nc] + bias) (* rowscale)
// W must be tf32-pre-rounded AND fragment-permuted (see roundW_kernel).
// 3-stage cp.async pipeline, 1 sync per K=16 chunk, 256 threads, warp 32x64.
// B fragment loads: 4 x LDS.128 per 8-k-step (vs 16 scalar LDS before).
// ===========================================================================
__device__ void tf32_gemm_v2(
    char* dyn, int bx, int by,
    const float* __restrict__ A, const float* __restrict__ W,
    const float* __restrict__ bias, const float* __restrict__ rowscale,
    float* __restrict__ C, int Nc)
{
    const int tid  = threadIdx.x;
    const int wid  = tid >> 5;
    const int lane = tid & 31;
    const int m0   = (wid & 3) * 32;
    const int wn   = wid >> 2;             // warp n-column (0/1)
    const int n0   = wn * 64;
    const int grp  = lane >> 2;
    const int q    = lane & 3;
    const int bm   = by * 128;
    const int bn   = bx * 128;

    const uint32_t sbase = smem_u32(dyn);

    float c[2][8][4];
    #pragma unroll
    for (int i = 0; i < 2; i++)
        #pragma unroll
        for (int j = 0; j < 8; j++)
            #pragma unroll
            for (int e = 0; e < 4; e++) c[i][j][e] = 0.f;

    // issue one chunk's cp.asyncs into stage s
    auto issue = [&](int ck, int s) {
        uint32_t As = sbase + s * STAGE_BYTES;
        uint32_t Bs = As + A_STAGE_BYTES;
        const int k0 = ck * 16;
        #pragma unroll
        for (int i = 0; i < 2; i++) {
            int idx = tid * 2 + i;                 // 0..511
            int row = idx >> 2, k4 = (idx & 3) << 2;
            cp_async16(As + (uint32_t)(row * 80 + k4 * 4),
                       &A[(size_t)(bm + row) * 256 + k0 + k4]);
        }
        // B: permuted global row-major -> smem [wn][grp][k][nf]
        #pragma unroll
        for (int i = 0; i < 2; i++) {
            int j = tid * 2 + i;                   // 0..511
            int k_rel = j >> 5;                    // 0..15
            int jj = j & 31;                       // float4 index within row
            int jwn = jj >> 4, jgrp = (jj >> 1) & 7, jh = jj & 1;
            uint32_t dst = Bs + (uint32_t)((jwn * 1056 + jgrp * 132 +
                                            k_rel * 8 + jh * 4) * 4);
            cp_async16(dst, &W[(size_t)(k0 + k_rel) * Nc + bn + jj * 4]);
        }
    };

    issue(0, 0); CP_COMMIT();
    issue(1, 1); CP_COMMIT();

    for (int ck = 0; ck < 16; ck++) {
        CP_WAIT1();
        __syncthreads();

        if (ck + 2 < 16) issue(ck + 2, (ck + 2) % 3);
        CP_COMMIT();                                  // empty groups in tail

        const int s = ck % 3;
        const float*    Am = (const float*)(dyn + s * STAGE_BYTES);       // [m][20]
        const uint32_t* Bp = (const uint32_t*)(dyn + s * STAGE_BYTES + A_STAGE_BYTES);
        const uint32_t* Bw = Bp + wn * 1056 + grp * 132;

        #pragma unroll
        for (int ks = 0; ks < 16; ks += 8) {
            uint32_t a[2][4];
            #pragma unroll
            for (int mf = 0; mf < 2; mf++) {
                int mr = m0 + mf * 16 + grp;
                a[mf][0] = f2tf32(Am[mr * 20 + ks + q]);
                a[mf][1] = f2tf32(Am[(mr + 8) * 20 + ks + q]);
                a[mf][2] = f2tf32(Am[mr * 20 + ks + q + 4]);
                a[mf][3] = f2tf32(Am[(mr + 8) * 20 + ks + q + 4]);
            }
            // B fragments: nf contiguous -> LDS.128
            uint4 t0 = *(const uint4*)(Bw + (ks + q) * 8);
            uint4 t1 = *(const uint4*)(Bw + (ks + q) * 8 + 4);
            uint4 t2 = *(const uint4*)(Bw + (ks + q + 4) * 8);
            uint4 t3 = *(const uint4*)(Bw + (ks + q + 4) * 8 + 4);
            uint32_t b[8][2] = {
                {t0.x, t2.x}, {t0.y, t2.y}, {t0.z, t2.z}, {t0.w, t2.w},
                {t1.x, t3.x}, {t1.y, t3.y}, {t1.z, t3.z}, {t1.w, t3.w}
            };
            #pragma unroll
            for (int mf = 0; mf < 2; mf++)
                #pragma unroll
                for (int nf = 0; nf < 8; nf++)
                    mma_tf32(c[mf][nf], a[mf][0], a[mf][1], a[mf][2], a[mf][3],
                             b[nf][0], b[nf][1]);
        }
        __syncthreads();
    }

    #pragma unroll
    for (int mf = 0; mf < 2; mf++) {
        int r0 = bm + m0 + mf * 16 + grp;
        int r1 = r0 + 8;
        float rs0 = rowscale ? rowscale[r0] : 1.f;
        float rs1 = rowscale ? rowscale[r1] : 1.f;
        #pragma unroll
        for (int nf = 0; nf < 8; nf++) {
            int col = bn + n0 + nf * 8 + 2 * q;
            float2 bv = *(const float2*)&bias[col];
            float2 lo = make_float2((c[mf][nf][0] + bv.x) * rs0,
                                    (c[mf][nf][1] + bv.y) * rs0);
            float2 hi = make_float2((c[mf][nf][2] + bv.x) * rs1,
                                    (c[mf][nf][3] + bv.y) * rs1);
            *(float2*)&C[(size_t)r0 * Nc + col] = lo;
            *(float2*)&C[(size_t)r1 * Nc + col] = hi;
        }
    }
}

// ===========================================================================
// f32x2 packed helpers
// ===========================================================================
__device__ __forceinline__ unsigned long long pack_dup(float v) {
    unsigned long long r;
    asm("mov.b64 %0, {%1, %1};" : "=l"(r) : "f"(v));
    return r;
}
__device__ __forceinline__ unsigned long long pack2(float lo, float hi) {
    unsigned long long r;
    asm("mov.b64 %0, {%1, %2};" : "=l"(r) : "f"(lo), "f"(hi));
    return r;
}
__device__ __forceinline__ float2 unpack2(unsigned long long v) {
    float2 r;
    asm("mov.b64 {%0, %1}, %2;" : "=f"(r.x), "=f"(r.y) : "l"(v));
    return r;
}
__device__ __forceinline__ void ffma2(unsigned long long& acc,
                                      unsigned long long a,
                                      unsigned long long b) {
    asm("fma.rn.f32x2 %0, %1, %2, %0;" : "+l"(acc) : "l"(a), "l"(b));
}

// ===========================================================================
// Exact fp32 SGEMM body (logits/deltas). Static smem (12.3KB, separate).
// ===========================================================================
__device__ void sgemm_body(
    int bx, int by,
    const float* __restrict__ A, const float* __restrict__ B,
    const float* __restrict__ bias, float* __restrict__ C, int Nc)
{
    __shared__ float Asf[16][128];
    __shared__ float Bsf[16][64];

    const int bm  = by * 128;
    const int bn  = bx * 64;
    const int tid = threadIdx.x;
    const int tr  = tid >> 4;
    const int tc  = tid & 15;

    unsigned long long acc2[4][4];
    #pragma unroll
    for (int i = 0; i < 4; i++)
        #pragma unroll
        for (int j = 0; j < 4; j++) acc2[i][j] = 0ULL;

    for (int k0 = 0; k0 < 256; k0 += 16) {
        #pragma unroll
        for (int i = 0; i < 2; i++) {
            int idx = tid * 2 + i;
            int row = idx >> 2;
            int c4  = (idx & 3) << 2;
            float4 v = *(const float4*)&A[(size_t)(bm + row) * 256 + k0 + c4];
            Asf[c4 + 0][row] = v.x;
            Asf[c4 + 1][row] = v.y;
            Asf[c4 + 2][row] = v.z;
            Asf[c4 + 3][row] = v.w;
        }
        {
            int row = tid >> 4;
            int c4  = (tid & 15) << 2;
            *(float4*)&Bsf[row][c4] =
                *(const float4*)&B[(size_t)(k0 + row) * Nc + bn + c4];
        }
        __syncthreads();

        #pragma unroll
        for (int k = 0; k < 16; k++) {
            unsigned long long aa[4], bb[4];
            #pragma unroll
            for (int i = 0; i < 4; i++) {
                float2 ap = *(const float2*)&Asf[k][tr * 8 + i * 2];
                aa[i] = pack2(ap.x, ap.y);
            }
            #pragma unroll
            for (int j = 0; j < 4; j++)
                bb[j] = pack_dup(Bsf[k][tc * 4 + j]);
            #pragma unroll
            for (int i = 0; i < 4; i++)
                #pragma unroll
                for (int j = 0; j < 4; j++)
                    ffma2(acc2[i][j], aa[i], bb[j]);
        }
        __syncthreads();
    }

    const int colb = bn + tc * 4;
    float4 bv = *(const float4*)&bias[colb];
    #pragma unroll
    for (int i = 0; i < 4; i++) {
        int row0 = bm + tr * 8 + i * 2;
        float2 c0 = unpack2(acc2[i][0]);
        float2 c1 = unpack2(acc2[i][1]);
        float2 c2 = unpack2(acc2[i][2]);
        float2 c3 = unpack2(acc2[i][3]);
        float4 lo = make_float4(c0.x + bv.x, c1.x + bv.y, c2.x + bv.z, c3.x + bv.w);
        float4 hi = make_float4(c0.y + bv.x, c1.y + bv.y, c2.y + bv.z, c3.y + bv.w);
        *(float4*)&C[(size_t)row0 * Nc + colb]       = lo;
        *(float4*)&C[(size_t)(row0 + 1) * Nc + colb] = hi;
    }
}

// ===========================================================================
// Weight prep: tf32 RNA round + fragment permutation.
// Within each 128-col half: source col n = wn*64 + nf*8 + grp
//   -> permuted pos p = wn*64 + grp*8 + nf  (nf contiguous for LDS.128)
// ===========================================================================
__global__ void __launch_bounds__(256) roundW_kernel(
    const float* __restrict__ W_val, const float* __restrict__ W_out)
{
    int i = blockIdx.x * 256 + threadIdx.x;      // 0..65535
    int k = i >> 8, n = i & 255;
    int half = n >> 7, r = n & 127;
    int wn = r >> 6, rr = r & 63;
    int nf = rr >> 3, grp = rr & 7;
    int p = half * 128 + wn * 64 + grp * 8 + nf;
    g_Wval_r[k * 256 + p] = __uint_as_float(f2tf32(W_val[i]));
    g_Wout_r[k * 256 + p] = __uint_as_float(f2tf32(W_out[i]));
}

// ===========================================================================
// Fused phase-1: heterogeneous CTAs
// ===========================================================================
__global__ void __launch_bounds__(256, 2) phase1_kernel(
    const float* __restrict__ value,   const float* __restrict__ b_val,
    const float* __restrict__ vmaskin, const float* __restrict__ queries,
    const float* __restrict__ W_attn,  const float* __restrict__ b_attn,
    const float* __restrict__ W_off,   const float* __restrict__ b_off)
{
    extern __shared__ char dyn[];
    int sid = (int)(((long long)blockIdx.x * 997) % N_TOT);
    if (sid < N_VM) {
        tf32_gemm_v2(dyn, sid & 1, sid >> 1, value, g_Wval_r, b_val, vmaskin,
                     g_vmask, 256);
    } else if (sid < N_VM + N_LG) {
        int t = sid - N_VM;
        sgemm_body(t & 1, t >> 1, queries, W_attn, b_attn, g_logits, 128);
    } else {
        int t = sid - N_VM - N_LG;
        sgemm_body(t & 3, t >> 2, queries, W_off, b_off, g_deltas, 256);
    }
}

// ===========================================================================
// Output projection: pipelined tf32 GEMM
// ===========================================================================
__global__ void __launch_bounds__(256, 2) outproj_kernel(
    const float* __restrict__ bias, float* __restrict__ out)
{
    extern __shared__ char dyn[];
    tf32_gemm_v2(dyn, blockIdx.x, blockIdx.y, g_mdv, g_Wout_r, bias, nullptr,
                 out, 256);
}

// ===========================================================================
// Sampling (LDG.128 per point, corner butterfly merge)
// ===========================================================================
__global__ void __launch_bounds__(256) sample_kernel(
    const float* __restrict__ geom)
{
    __shared__ int4   sI[8][16];
    __shared__ float4 sW[8][16];

    const int nq = blockIdx.x;
    const int n  = nq / SQ;
    const int t  = threadIdx.x;

    if (t < 128) {
        const int m = t >> 4;
        const int p = t & 15;

        float cx = 1.f / (1.f + __expf(-geom[nq * 4 + 0]));
        float cy = 1.f / (1.f + __expf(-geom[nq * 4 + 1]));
        float sw = 0.125f / (1.f + __expf(-geom[nq * 4 + 2]));
        float sh = 0.125f / (1.f + __expf(-geom[nq * 4 + 3]));

        float l = g_logits[(size_t)nq * 128 + m * 16 + p];
        float mx = l;
        #pragma unroll
        for (int d = 8; d >= 1; d >>= 1)
            mx = fmaxf(mx, __shfl_xor_sync(0xffffffffu, mx, d, 16));
        float e = __expf(l - mx);
        float s = e;
        #pragma unroll
        for (int d = 8; d >= 1; d >>= 1)
            s += __shfl_xor_sync(0xffffffffu, s, d, 16);
        const float a = e / s;

        const float dx = g_deltas[(size_t)nq * 256 + m * 32 + 2 * p];
        const float dy = g_deltas[(size_t)nq * 256 + m * 32 + 2 * p + 1];

        const int li = p >> 2;
        const int HW = 128 >> li;
        const int starts[4] = {0, 16384, 20480, 21504};
        const int start = starts[li];

        float px = fmaf(dx, sw, cx);
        float py = fmaf(dy, sh, cy);
        float gx = fminf(fmaxf(2.f * px - 1.f, -1.f), 1.f);
        float gy = fminf(fmaxf(2.f * py - 1.f, -1.f), 1.f);
        float x = (gx + 1.f) * (HW * 0.5f) - 0.5f;
        float y = (gy + 1.f) * (HW * 0.5f) - 0.5f;
        float x0f = floorf(x), y0f = floorf(y);
        float wx = x - x0f, wy = y - y0f;
        int x0 = (int)x0f, y0 = (int)y0f;
        int x1 = x0 + 1,  y1 = y0 + 1;

        bool vx0 = (x0 >= 0) & (x0 < HW);
        bool vx1 = (x1 >= 0) & (x1 < HW);
        bool vy0 = (y0 >= 0) & (y0 < HW);
        bool vy1 = (y1 >= 0) & (y1 < HW);

        int4 idx;
        float4 w;
        idx.x = (vx0 & vy0) ? (start + y0 * HW + x0) * 256 : 0;
        idx.y = (vx1 & vy0) ? (start + y0 * HW + x1) * 256 : 0;
        idx.z = (vx0 & vy1) ? (start + y1 * HW + x0) * 256 : 0;
        idx.w = (vx1 & vy1) ? (start + y1 * HW + x1) * 256 : 0;
        w.x = (vx0 & vy0) ? a * (1.f - wx) * (1.f - wy) : 0.f;
        w.y = (vx1 & vy0) ? a * wx * (1.f - wy)         : 0.f;
        w.z = (vx0 & vy1) ? a * (1.f - wx) * wy         : 0.f;
        w.w = (vx1 & vy1) ? a * wx * wy                 : 0.f;

        sI[m][p] = idx;
        sW[m][p] = w;
    }
    __syncthreads();

    const int m      = t >> 5;
    const int lane   = t & 31;
    const int corner = lane >> 3;
    const int cb     = lane & 7;
    const float* __restrict__ vb4 =
        g_vmask + (size_t)n * S_TOT * 256 + m * 32 + cb * 4;
    const int*   __restrict__ pI = (const int*)&sI[m][0]   + corner;
    const float* __restrict__ pW = (const float*)&sW[m][0] + corner;

    float4 acc = make_float4(0.f, 0.f, 0.f, 0.f);
    #pragma unroll
    for (int p = 0; p < 16; p++) {
        int   I = pI[4 * p];
        float w = pW[4 * p];
        float4 v = *(const float4*)(vb4 + I);
        acc.x = fmaf(w, v.x, acc.x);
        acc.y = fmaf(w, v.y, acc.y);
        acc.z = fmaf(w, v.z, acc.z);
        acc.w = fmaf(w, v.w, acc.w);
    }

    #pragma unroll
    for (int d = 8; d <= 16; d <<= 1) {
        acc.x += __shfl_xor_sync(0xffffffffu, acc.x, d);
        acc.y += __shfl_xor_sync(0xffffffffu, acc.y, d);
        acc.z += __shfl_xor_sync(0xffffffffu, acc.z, d);
        acc.w += __shfl_xor_sync(0xffffffffu, acc.w, d);
    }
    if (lane < 8)
        *(float4*)&g_mdv[(size_t)nq * 256 + m * 32 + cb * 4] = acc;
}

// ===========================================================================
// Launch
// ===========================================================================
extern "C" void kernel_launch(void* const* d_in, const int* in_sizes, int n_in,
                              void* d_out, int out_size)
{
    const float* queries = (const float*)d_in[0];
    const float* geom    = (const float*)d_in[1];
    const float* value   = (const float*)d_in[2];
    const float* vmaskin = (const float*)d_in[3];
    const float* W_off   = (const float*)d_in[4];
    const float* b_off   = (const float*)d_in[5];
    const float* W_attn  = (const float*)d_in[6];
    const float* b_attn  = (const float*)d_in[7];
    const float* W_val   = (const float*)d_in[8];
    const float* b_val   = (const float*)d_in[9];
    const float* W_out   = (const float*)d_in[10];
    const float* b_out   = (const float*)d_in[11];
    float* out = (float*)d_out;

    static int attr_done = 0;
    if (!attr_done) {
        cudaFuncSetAttribute(phase1_kernel,
                             cudaFuncAttributeMaxDynamicSharedMemorySize,
                             TF32_DSMEM);
        cudaFuncSetAttribute(outproj_kernel,
                             cudaFuncAttributeMaxDynamicSharedMemorySize,
                             TF32_DSMEM);
        attr_done = 1;
    }

    // Pre-round + permute weights for the tensor-core B path
    roundW_kernel<<<256, 256>>>(W_val, W_out);
    // Phase 1 (fused): vmask tf32-MMA + logits/deltas exact fp32
    phase1_kernel<<<N_TOT, 256, TF32_DSMEM>>>(value, b_val, vmaskin,
                                              queries, W_attn, b_attn,
                                              W_off, b_off);
    // Phase 2: sampling -> g_mdv
    sample_kernel<<<NQ, 256>>>(geom);
    // Phase 3: out = mdv @ W_out + b_out (tf32 MMA, pipelined)
    outproj_kernel<<<dim3(2, NQ / 128), 256, TF32_DSMEM>>>(b_out, out);
}

// round 15
// speedup vs baseline: 1.0259x; 1.0259x over previous
#include <cuda_runtime.h>
#include <math.h>
#include <stdint.h>

#define SQ      8192
#define NBATCH  2
#define S_TOT   21760
#define NQ      (NBATCH*SQ)      // 16384
#define NS      (NBATCH*S_TOT)   // 43520

// tf32 pipeline smem geometry (R13-proven)
#define A_STAGE_BYTES  (128*20*4)              // [m][20] stride-20 pad
#define B_STAGE_BYTES  (16*136*4)              // [k][136]
#define STAGE_BYTES    (A_STAGE_BYTES + B_STAGE_BYTES)   // 18944
#define TF32_DSMEM     (3 * STAGE_BYTES)                 // 56832

// Scratch (device globals: referenced ONLY inside device code — passing
// these as host-side kernel args was the R10-12 corruption bug)
__device__ float g_vmask [(size_t)NS*256];
__device__ float g_logits[(size_t)NQ*128];
__device__ float g_deltas[(size_t)NQ*256];
__device__ float g_mdv   [(size_t)NQ*256];
__device__ float g_Wval_r[256*256];   // tf32-RNA pre-rounded weights
__device__ float g_Wout_r[256*256];

// ===========================================================================
// PTX helpers
// ===========================================================================
__device__ __forceinline__ uint32_t f2tf32(float v) {
    uint32_t r;
    asm("cvt.rna.tf32.f32 %0, %1;" : "=r"(r) : "f"(v));
    return r;
}
__device__ __forceinline__ void mma_tf32(float c[4],
                                         uint32_t a0, uint32_t a1,
                                         uint32_t a2, uint32_t a3,
                                         uint32_t b0, uint32_t b1) {
    asm volatile(
        "mma.sync.aligned.m16n8k8.row.col.f32.tf32.tf32.f32 "
        "{%0,%1,%2,%3}, {%4,%5,%6,%7}, {%8,%9}, {%0,%1,%2,%3};"
        : "+f"(c[0]), "+f"(c[1]), "+f"(c[2]), "+f"(c[3])
        : "r"(a0), "r"(a1), "r"(a2), "r"(a3), "r"(b0), "r"(b1));
}
__device__ __forceinline__ uint32_t smem_u32(const void* p) {
    uint32_t a;
    asm("{ .reg .u64 t; cvta.to.shared.u64 t, %1; cvt.u32.u64 %0, t; }"
        : "=r"(a) : "l"(p));
    return a;
}
__device__ __forceinline__ void cp_async16(uint32_t dst, const void* src) {
    asm volatile("cp.async.cg.shared.global [%0], [%1], 16;"
                 :: "r"(dst), "l"(src));
}
#define CP_COMMIT() asm volatile("cp.async.commit_group;" ::: "memory")
#define CP_WAIT1()  asm volatile("cp.async.wait_group 1;" ::: "memory")

// ===========================================================================
// Pipelined tf32 GEMM body (R13-proven, unpermuted):
//   C[.. x Nc] = (A[.. x 256] @ W[256 x Nc] + bias) (* rowscale)
// ===========================================================================
__device__ void tf32_gemm_v2(
    char* dyn, int bx, int by,
    const float* __restrict__ A, const float* __restrict__ W,
    const float* __restrict__ bias, const float* __restrict__ rowscale,
    float* __restrict__ C, int Nc)
{
    const int tid  = threadIdx.x;
    const int wid  = tid >> 5;
    const int lane = tid & 31;
    const int m0   = (wid & 3) * 32;
    const int n0   = (wid >> 2) * 64;
    const int grp  = lane >> 2;
    const int q    = lane & 3;
    const int bm   = by * 128;
    const int bn   = bx * 128;

    const uint32_t sbase = smem_u32(dyn);

    float c[2][8][4];
    #pragma unroll
    for (int i = 0; i < 2; i++)
        #pragma unroll
        for (int j = 0; j < 8; j++)
            #pragma unroll
            for (int e = 0; e < 4; e++) c[i][j][e] = 0.f;

    auto issue = [&](int ck, int s) {
        uint32_t As = sbase + s * STAGE_BYTES;
        uint32_t Bs = As + A_STAGE_BYTES;
        const int k0 = ck * 16;
        #pragma unroll
        for (int i = 0; i < 2; i++) {
            int idx = tid * 2 + i;
            int row = idx >> 2, k4 = (idx & 3) << 2;
            cp_async16(As + (uint32_t)(row * 80 + k4 * 4),
                       &A[(size_t)(bm + row) * 256 + k0 + k4]);
        }
        #pragma unroll
        for (int i = 0; i < 2; i++) {
            int idx = tid * 2 + i;
            int kr = idx >> 5, nc = (idx & 31) << 2;
            cp_async16(Bs + (uint32_t)(kr * 544 + nc * 4),
                       &W[(size_t)(k0 + kr) * Nc + bn + nc]);
        }
    };

    issue(0, 0); CP_COMMIT();
    issue(1, 1); CP_COMMIT();

    for (int ck = 0; ck < 16; ck++) {
        CP_WAIT1();
        __syncthreads();

        if (ck + 2 < 16) issue(ck + 2, (ck + 2) % 3);
        CP_COMMIT();

        const int s = ck % 3;
        const float*    Am = (const float*)(dyn + s * STAGE_BYTES);
        const uint32_t* Bk = (const uint32_t*)(dyn + s * STAGE_BYTES + A_STAGE_BYTES);

        #pragma unroll
        for (int ks = 0; ks < 16; ks += 8) {
            uint32_t a[2][4];
            #pragma unroll
            for (int mf = 0; mf < 2; mf++) {
                int mr = m0 + mf * 16 + grp;
                a[mf][0] = f2tf32(Am[mr * 20 + ks + q]);
                a[mf][1] = f2tf32(Am[(mr + 8) * 20 + ks + q]);
                a[mf][2] = f2tf32(Am[mr * 20 + ks + q + 4]);
                a[mf][3] = f2tf32(Am[(mr + 8) * 20 + ks + q + 4]);
            }
            uint32_t b[8][2];
            #pragma unroll
            for (int nf = 0; nf < 8; nf++) {
                int nb = n0 + nf * 8 + grp;
                b[nf][0] = Bk[(ks + q) * 136 + nb];
                b[nf][1] = Bk[(ks + q + 4) * 136 + nb];
            }
            #pragma unroll
            for (int mf = 0; mf < 2; mf++)
                #pragma unroll
                for (int nf = 0; nf < 8; nf++)
                    mma_tf32(c[mf][nf], a[mf][0], a[mf][1], a[mf][2], a[mf][3],
                             b[nf][0], b[nf][1]);
        }
        __syncthreads();
    }

    #pragma unroll
    for (int mf = 0; mf < 2; mf++) {
        int r0 = bm + m0 + mf * 16 + grp;
        int r1 = r0 + 8;
        float rs0 = rowscale ? rowscale[r0] : 1.f;
        float rs1 = rowscale ? rowscale[r1] : 1.f;
        #pragma unroll
        for (int nf = 0; nf < 8; nf++) {
            int col = bn + n0 + nf * 8 + 2 * q;
            float2 bv = *(const float2*)&bias[col];
            float2 lo = make_float2((c[mf][nf][0] + bv.x) * rs0,
                                    (c[mf][nf][1] + bv.y) * rs0);
            float2 hi = make_float2((c[mf][nf][2] + bv.x) * rs1,
                                    (c[mf][nf][3] + bv.y) * rs1);
            *(float2*)&C[(size_t)r0 * Nc + col] = lo;
            *(float2*)&C[(size_t)r1 * Nc + col] = hi;
        }
    }
}

// ===========================================================================
// f32x2 packed helpers
// ===========================================================================
__device__ __forceinline__ unsigned long long pack_dup(float v) {
    unsigned long long r;
    asm("mov.b64 %0, {%1, %1};" : "=l"(r) : "f"(v));
    return r;
}
__device__ __forceinline__ unsigned long long pack2(float lo, float hi) {
    unsigned long long r;
    asm("mov.b64 %0, {%1, %2};" : "=l"(r) : "f"(lo), "f"(hi));
    return r;
}
__device__ __forceinline__ float2 unpack2(unsigned long long v) {
    float2 r;
    asm("mov.b64 {%0, %1}, %2;" : "=f"(r.x), "=f"(r.y) : "l"(v));
    return r;
}
__device__ __forceinline__ void ffma2(unsigned long long& acc,
                                      unsigned long long a,
                                      unsigned long long b) {
    asm("fma.rn.f32x2 %0, %1, %2, %0;" : "+l"(acc) : "l"(a), "l"(b));
}

// ===========================================================================
// Exact fp32 SGEMM body (logits/deltas)
// ===========================================================================
__device__ void sgemm_body(
    int bx, int by,
    const float* __restrict__ A, const float* __restrict__ B,
    const float* __restrict__ bias, float* __restrict__ C, int Nc)
{
    __shared__ float Asf[16][128];
    __shared__ float Bsf[16][64];

    const int bm  = by * 128;
    const int bn  = bx * 64;
    const int tid = threadIdx.x;
    const int tr  = tid >> 4;
    const int tc  = tid & 15;

    unsigned long long acc2[4][4];
    #pragma unroll
    for (int i = 0; i < 4; i++)
        #pragma unroll
        for (int j = 0; j < 4; j++) acc2[i][j] = 0ULL;

    for (int k0 = 0; k0 < 256; k0 += 16) {
        #pragma unroll
        for (int i = 0; i < 2; i++) {
            int idx = tid * 2 + i;
            int row = idx >> 2;
            int c4  = (idx & 3) << 2;
            float4 v = *(const float4*)&A[(size_t)(bm + row) * 256 + k0 + c4];
            Asf[c4 + 0][row] = v.x;
            Asf[c4 + 1][row] = v.y;
            Asf[c4 + 2][row] = v.z;
            Asf[c4 + 3][row] = v.w;
        }
        {
            int row = tid >> 4;
            int c4  = (tid & 15) << 2;
            *(float4*)&Bsf[row][c4] =
                *(const float4*)&B[(size_t)(k0 + row) * Nc + bn + c4];
        }
        __syncthreads();

        #pragma unroll
        for (int k = 0; k < 16; k++) {
            unsigned long long aa[4], bb[4];
            #pragma unroll
            for (int i = 0; i < 4; i++) {
                float2 ap = *(const float2*)&Asf[k][tr * 8 + i * 2];
                aa[i] = pack2(ap.x, ap.y);
            }
            #pragma unroll
            for (int j = 0; j < 4; j++)
                bb[j] = pack_dup(Bsf[k][tc * 4 + j]);
            #pragma unroll
            for (int i = 0; i < 4; i++)
                #pragma unroll
                for (int j = 0; j < 4; j++)
                    ffma2(acc2[i][j], aa[i], bb[j]);
        }
        __syncthreads();
    }

    const int colb = bn + tc * 4;
    float4 bv = *(const float4*)&bias[colb];
    #pragma unroll
    for (int i = 0; i < 4; i++) {
        int row0 = bm + tr * 8 + i * 2;
        float2 c0 = unpack2(acc2[i][0]);
        float2 c1 = unpack2(acc2[i][1]);
        float2 c2 = unpack2(acc2[i][2]);
        float2 c3 = unpack2(acc2[i][3]);
        float4 lo = make_float4(c0.x + bv.x, c1.x + bv.y, c2.x + bv.z, c3.x + bv.w);
        float4 hi = make_float4(c0.y + bv.x, c1.y + bv.y, c2.y + bv.z, c3.y + bv.w);
        *(float4*)&C[(size_t)row0 * Nc + colb]       = lo;
        *(float4*)&C[(size_t)(row0 + 1) * Nc + colb] = hi;
    }
}

// ===========================================================================
// Standalone kernels — scratch globals referenced in DEVICE code only
// ===========================================================================
__global__ void __launch_bounds__(256) roundW_kernel(
    const float* __restrict__ W_val, const float* __restrict__ W_out)
{
    int i = blockIdx.x * 256 + threadIdx.x;
    g_Wval_r[i] = __uint_as_float(f2tf32(W_val[i]));
    g_Wout_r[i] = __uint_as_float(f2tf32(W_out[i]));
}

__global__ void __launch_bounds__(256, 2) vmask_kernel(
    const float* __restrict__ value, const float* __restrict__ b_val,
    const float* __restrict__ vmaskin)
{
    extern __shared__ char dyn[];
    tf32_gemm_v2(dyn, blockIdx.x, blockIdx.y, value, g_Wval_r, b_val, vmaskin,
                 g_vmask, 256);
}

__global__ void __launch_bounds__(256) logits_kernel(
    const float* __restrict__ queries, const float* __restrict__ W_attn,
    const float* __restrict__ b_attn)
{
    sgemm_body(blockIdx.x, blockIdx.y, queries, W_attn, b_attn, g_logits, 128);
}

__global__ void __launch_bounds__(256) deltas_kernel(
    const float* __restrict__ queries, const float* __restrict__ W_off,
    const float* __restrict__ b_off)
{
    sgemm_body(blockIdx.x, blockIdx.y, queries, W_off, b_off, g_deltas, 256);
}

__global__ void __launch_bounds__(256, 2) outproj_kernel(
    const float* __restrict__ bias, float* __restrict__ out)
{
    extern __shared__ char dyn[];
    tf32_gemm_v2(dyn, blockIdx.x, blockIdx.y, g_mdv, g_Wout_r, bias, nullptr,
                 out, 256);
}

// ===========================================================================
// Sampling (LDG.128 per point, corner butterfly merge)
// ===========================================================================
__global__ void __launch_bounds__(256) sample_kernel(
    const float* __restrict__ geom)
{
    __shared__ int4   sI[8][16];
    __shared__ float4 sW[8][16];

    const int nq = blockIdx.x;
    const int n  = nq / SQ;
    const int t  = threadIdx.x;

    if (t < 128) {
        const int m = t >> 4;
        const int p = t & 15;

        float cx = 1.f / (1.f + __expf(-geom[nq * 4 + 0]));
        float cy = 1.f / (1.f + __expf(-geom[nq * 4 + 1]));
        float sw = 0.125f / (1.f + __expf(-geom[nq * 4 + 2]));
        float sh = 0.125f / (1.f + __expf(-geom[nq * 4 + 3]));

        float l = g_logits[(size_t)nq * 128 + m * 16 + p];
        float mx = l;
        #pragma unroll
        for (int d = 8; d >= 1; d >>= 1)
            mx = fmaxf(mx, __shfl_xor_sync(0xffffffffu, mx, d, 16));
        float e = __expf(l - mx);
        float s = e;
        #pragma unroll
        for (int d = 8; d >= 1; d >>= 1)
            s += __shfl_xor_sync(0xffffffffu, s, d, 16);
        const float a = e / s;

        const float dx = g_deltas[(size_t)nq * 256 + m * 32 + 2 * p];
        const float dy = g_deltas[(size_t)nq * 256 + m * 32 + 2 * p + 1];

        const int li = p >> 2;
        const int HW = 128 >> li;
        const int starts[4] = {0, 16384, 20480, 21504};
        const int start = starts[li];

        float px = fmaf(dx, sw, cx);
        float py = fmaf(dy, sh, cy);
        float gx = fminf(fmaxf(2.f * px - 1.f, -1.f), 1.f);
        float gy = fminf(fmaxf(2.f * py - 1.f, -1.f), 1.f);
        float x = (gx + 1.f) * (HW * 0.5f) - 0.5f;
        float y = (gy + 1.f) * (HW * 0.5f) - 0.5f;
        float x0f = floorf(x), y0f = floorf(y);
        float wx = x - x0f, wy = y - y0f;
        int x0 = (int)x0f, y0 = (int)y0f;
        int x1 = x0 + 1,  y1 = y0 + 1;

        bool vx0 = (x0 >= 0) & (x0 < HW);
        bool vx1 = (x1 >= 0) & (x1 < HW);
        bool vy0 = (y0 >= 0) & (y0 < HW);
        bool vy1 = (y1 >= 0) & (y1 < HW);

        int4 idx;
        float4 w;
        idx.x = (vx0 & vy0) ? (start + y0 * HW + x0) * 256 : 0;
        idx.y = (vx1 & vy0) ? (start + y0 * HW + x1) * 256 : 0;
        idx.z = (vx0 & vy1) ? (start + y1 * HW + x0) * 256 : 0;
        idx.w = (vx1 & vy1) ? (start + y1 * HW + x1) * 256 : 0;
        w.x = (vx0 & vy0) ? a * (1.f - wx) * (1.f - wy) : 0.f;
        w.y = (vx1 & vy0) ? a * wx * (1.f - wy)         : 0.f;
        w.z = (vx0 & vy1) ? a * (1.f - wx) * wy         : 0.f;
        w.w = (vx1 & vy1) ? a * wx * wy                 : 0.f;

        sI[m][p] = idx;
        sW[m][p] = w;
    }
    __syncthreads();

    const int m      = t >> 5;
    const int lane   = t & 31;
    const int corner = lane >> 3;
    const int cb     = lane & 7;
    const float* __restrict__ vb4 =
        g_vmask + (size_t)n * S_TOT * 256 + m * 32 + cb * 4;
    const int*   __restrict__ pI = (const int*)&sI[m][0]   + corner;
    const float* __restrict__ pW = (const float*)&sW[m][0] + corner;

    float4 acc = make_float4(0.f, 0.f, 0.f, 0.f);
    #pragma unroll
    for (int p = 0; p < 16; p++) {
        int   I = pI[4 * p];
        float w = pW[4 * p];
        float4 v = *(const float4*)(vb4 + I);
        acc.x = fmaf(w, v.x, acc.x);
        acc.y = fmaf(w, v.y, acc.y);
        acc.z = fmaf(w, v.z, acc.z);
        acc.w = fmaf(w, v.w, acc.w);
    }

    #pragma unroll
    for (int d = 8; d <= 16; d <<= 1) {
        acc.x += __shfl_xor_sync(0xffffffffu, acc.x, d);
        acc.y += __shfl_xor_sync(0xffffffffu, acc.y, d);
        acc.z += __shfl_xor_sync(0xffffffffu, acc.z, d);
        acc.w += __shfl_xor_sync(0xffffffffu, acc.w, d);
    }
    if (lane < 8)
        *(float4*)&g_mdv[(size_t)nq * 256 + m * 32 + cb * 4] = acc;
}

// ===========================================================================
// Launch — fork/join: s1 carries tensor-pipe work, main carries fma GEMMs
// ===========================================================================
extern "C" void kernel_launch(void* const* d_in, const int* in_sizes, int n_in,
                              void* d_out, int out_size)
{
    const float* queries = (const float*)d_in[0];
    const float* geom    = (const float*)d_in[1];
    const float* value   = (const float*)d_in[2];
    const float* vmaskin = (const float*)d_in[3];
    const float* W_off   = (const float*)d_in[4];
    const float* b_off   = (const float*)d_in[5];
    const float* W_attn  = (const float*)d_in[6];
    const float* b_attn  = (const float*)d_in[7];
    const float* W_val   = (const float*)d_in[8];
    const float* b_val   = (const float*)d_in[9];
    const float* W_out   = (const float*)d_in[10];
    const float* b_out   = (const float*)d_in[11];
    float* out = (float*)d_out;

    static cudaStream_t s1 = nullptr;
    static cudaEvent_t  ev_fork = nullptr, ev_join = nullptr;
    static int init_done = 0;
    if (!init_done) {
        cudaStreamCreateWithFlags(&s1, cudaStreamNonBlocking);
        cudaEventCreateWithFlags(&ev_fork, cudaEventDisableTiming);
        cudaEventCreateWithFlags(&ev_join, cudaEventDisableTiming);
        cudaFuncSetAttribute(vmask_kernel,
                             cudaFuncAttributeMaxDynamicSharedMemorySize,
                             TF32_DSMEM);
        cudaFuncSetAttribute(outproj_kernel,
                             cudaFuncAttributeMaxDynamicSharedMemorySize,
                             TF32_DSMEM);
        init_done = 1;
    }

    // Fork: branch s1 = tensor-pipe work (roundW -> vmask GEMM)
    cudaEventRecord(ev_fork, 0);
    cudaStreamWaitEvent(s1, ev_fork, 0);

    roundW_kernel<<<256, 256, 0, s1>>>(W_val, W_out);
    vmask_kernel<<<dim3(2, NS / 128), 256, TF32_DSMEM, s1>>>(value, b_val,
                                                             vmaskin);

    // Main stream: fma-pipe exact GEMMs run concurrently with s1
    logits_kernel<<<dim3(2, NQ / 128), 256>>>(queries, W_attn, b_attn);
    deltas_kernel<<<dim3(4, NQ / 128), 256>>>(queries, W_off, b_off);

    // Join s1 back into main before sampling
    cudaEventRecord(ev_join, s1);
    cudaStreamWaitEvent(0, ev_join, 0);

    // Sampling -> g_mdv
    sample_kernel<<<NQ, 256>>>(geom);
    // out = mdv @ W_out + b_out (tf32 MMA)
    outproj_kernel<<<dim3(2, NQ / 128), 256, TF32_DSMEM>>>(b_out, out);
}

// round 16
// speedup vs baseline: 1.1339x; 1.1053x over previous
#include <cuda_runtime.h>
#include <math.h>
#include <stdint.h>

#define SQ      8192
#define NBATCH  2
#define S_TOT   21760
#define NQ      (NBATCH*SQ)      // 16384
#define NS      (NBATCH*S_TOT)   // 43520

// Fused phase-1 grid: 680 tf32-vmask CTAs + 256 logits CTAs + 512 deltas CTAs
#define N_VM   680
#define N_LG   256
#define N_DL   512
#define N_TOT  1448

// tf32 pipeline smem geometry
#define A_STAGE_BYTES  (128*20*4)              // [m][20] stride-20 pad
#define B_STAGE_BYTES  (16*136*4)              // [k][136]
#define STAGE_BYTES    (A_STAGE_BYTES + B_STAGE_BYTES)   // 18944
#define TF32_DSMEM     (3 * STAGE_BYTES)                 // 56832

// Scratch (device globals: referenced ONLY inside device code)
__device__ float g_vmask [(size_t)NS*256];
__device__ float g_logits[(size_t)NQ*128];
__device__ float g_deltas[(size_t)NQ*256];
__device__ float g_mdv   [(size_t)NQ*256];
__device__ float g_Wval_r[256*256];   // tf32-RNA pre-rounded weights
__device__ float g_Wout_r[256*256];

// ===========================================================================
// PTX helpers
// ===========================================================================
__device__ __forceinline__ uint32_t f2tf32(float v) {
    uint32_t r;
    asm("cvt.rna.tf32.f32 %0, %1;" : "=r"(r) : "f"(v));
    return r;
}
__device__ __forceinline__ void mma_tf32(float c[4],
                                         uint32_t a0, uint32_t a1,
                                         uint32_t a2, uint32_t a3,
                                         uint32_t b0, uint32_t b1) {
    asm volatile(
        "mma.sync.aligned.m16n8k8.row.col.f32.tf32.tf32.f32 "
        "{%0,%1,%2,%3}, {%4,%5,%6,%7}, {%8,%9}, {%0,%1,%2,%3};"
        : "+f"(c[0]), "+f"(c[1]), "+f"(c[2]), "+f"(c[3])
        : "r"(a0), "r"(a1), "r"(a2), "r"(a3), "r"(b0), "r"(b1));
}
__device__ __forceinline__ uint32_t smem_u32(const void* p) {
    uint32_t a;
    asm("{ .reg .u64 t; cvta.to.shared.u64 t, %1; cvt.u32.u64 %0, t; }"
        : "=r"(a) : "l"(p));
    return a;
}
__device__ __forceinline__ void cp_async16(uint32_t dst, const void* src) {
    asm volatile("cp.async.cg.shared.global [%0], [%1], 16;"
                 :: "r"(dst), "l"(src));
}
#define CP_COMMIT() asm volatile("cp.async.commit_group;" ::: "memory")
#define CP_WAIT1()  asm volatile("cp.async.wait_group 1;" ::: "memory")

// ===========================================================================
// Pipelined tf32 GEMM body (R13-proven):
//   C[.. x Nc] = (A[.. x 256] @ W[256 x Nc] + bias) (* rowscale)
// ===========================================================================
__device__ void tf32_gemm_v2(
    char* dyn, int bx, int by,
    const float* __restrict__ A, const float* __restrict__ W,
    const float* __restrict__ bias, const float* __restrict__ rowscale,
    float* __restrict__ C, int Nc)
{
    const int tid  = threadIdx.x;
    const int wid  = tid >> 5;
    const int lane = tid & 31;
    const int m0   = (wid & 3) * 32;
    const int n0   = (wid >> 2) * 64;
    const int grp  = lane >> 2;
    const int q    = lane & 3;
    const int bm   = by * 128;
    const int bn   = bx * 128;

    const uint32_t sbase = smem_u32(dyn);

    float c[2][8][4];
    #pragma unroll
    for (int i = 0; i < 2; i++)
        #pragma unroll
        for (int j = 0; j < 8; j++)
            #pragma unroll
            for (int e = 0; e < 4; e++) c[i][j][e] = 0.f;

    auto issue = [&](int ck, int s) {
        uint32_t As = sbase + s * STAGE_BYTES;
        uint32_t Bs = As + A_STAGE_BYTES;
        const int k0 = ck * 16;
        #pragma unroll
        for (int i = 0; i < 2; i++) {
            int idx = tid * 2 + i;
            int row = idx >> 2, k4 = (idx & 3) << 2;
            cp_async16(As + (uint32_t)(row * 80 + k4 * 4),
                       &A[(size_t)(bm + row) * 256 + k0 + k4]);
        }
        #pragma unroll
        for (int i = 0; i < 2; i++) {
            int idx = tid * 2 + i;
            int kr = idx >> 5, nc = (idx & 31) << 2;
            cp_async16(Bs + (uint32_t)(kr * 544 + nc * 4),
                       &W[(size_t)(k0 + kr) * Nc + bn + nc]);
        }
    };

    issue(0, 0); CP_COMMIT();
    issue(1, 1); CP_COMMIT();

    for (int ck = 0; ck < 16; ck++) {
        CP_WAIT1();
        __syncthreads();

        if (ck + 2 < 16) issue(ck + 2, (ck + 2) % 3);
        CP_COMMIT();

        const int s = ck % 3;
        const float*    Am = (const float*)(dyn + s * STAGE_BYTES);
        const uint32_t* Bk = (const uint32_t*)(dyn + s * STAGE_BYTES + A_STAGE_BYTES);

        #pragma unroll
        for (int ks = 0; ks < 16; ks += 8) {
            uint32_t a[2][4];
            #pragma unroll
            for (int mf = 0; mf < 2; mf++) {
                int mr = m0 + mf * 16 + grp;
                a[mf][0] = f2tf32(Am[mr * 20 + ks + q]);
                a[mf][1] = f2tf32(Am[(mr + 8) * 20 + ks + q]);
                a[mf][2] = f2tf32(Am[mr * 20 + ks + q + 4]);
                a[mf][3] = f2tf32(Am[(mr + 8) * 20 + ks + q + 4]);
            }
            uint32_t b[8][2];
            #pragma unroll
            for (int nf = 0; nf < 8; nf++) {
                int nb = n0 + nf * 8 + grp;
                b[nf][0] = Bk[(ks + q) * 136 + nb];
                b[nf][1] = Bk[(ks + q + 4) * 136 + nb];
            }
            #pragma unroll
            for (int mf = 0; mf < 2; mf++)
                #pragma unroll
                for (int nf = 0; nf < 8; nf++)
                    mma_tf32(c[mf][nf], a[mf][0], a[mf][1], a[mf][2], a[mf][3],
                             b[nf][0], b[nf][1]);
        }
        __syncthreads();
    }

    #pragma unroll
    for (int mf = 0; mf < 2; mf++) {
        int r0 = bm + m0 + mf * 16 + grp;
        int r1 = r0 + 8;
        float rs0 = rowscale ? rowscale[r0] : 1.f;
        float rs1 = rowscale ? rowscale[r1] : 1.f;
        #pragma unroll
        for (int nf = 0; nf < 8; nf++) {
            int col = bn + n0 + nf * 8 + 2 * q;
            float2 bv = *(const float2*)&bias[col];
            float2 lo = make_float2((c[mf][nf][0] + bv.x) * rs0,
                                    (c[mf][nf][1] + bv.y) * rs0);
            float2 hi = make_float2((c[mf][nf][2] + bv.x) * rs1,
                                    (c[mf][nf][3] + bv.y) * rs1);
            *(float2*)&C[(size_t)r0 * Nc + col] = lo;
            *(float2*)&C[(size_t)r1 * Nc + col] = hi;
        }
    }
}

// ===========================================================================
// f32x2 packed helpers
// ===========================================================================
__device__ __forceinline__ unsigned long long pack_dup(float v) {
    unsigned long long r;
    asm("mov.b64 %0, {%1, %1};" : "=l"(r) : "f"(v));
    return r;
}
__device__ __forceinline__ unsigned long long pack2(float lo, float hi) {
    unsigned long long r;
    asm("mov.b64 %0, {%1, %2};" : "=l"(r) : "f"(lo), "f"(hi));
    return r;
}
__device__ __forceinline__ float2 unpack2(unsigned long long v) {
    float2 r;
    asm("mov.b64 {%0, %1}, %2;" : "=f"(r.x), "=f"(r.y) : "l"(v));
    return r;
}
__device__ __forceinline__ void ffma2(unsigned long long& acc,
                                      unsigned long long a,
                                      unsigned long long b) {
    asm("fma.rn.f32x2 %0, %1, %2, %0;" : "+l"(acc) : "l"(a), "l"(b));
}

// ===========================================================================
// Exact fp32 SGEMM body (logits/deltas) — v2:
//   * register double-buffering of the global tiles (LDG latency hidden
//     under the 16 k-step compute)
//   * B fragments read as one LDS.128 (conflict-free phases) instead of
//     4 scalar LDS with a 2-way bank conflict
// Store/compute order identical to v1 -> bit-identical results.
// ===========================================================================
__device__ void sgemm_body(
    int bx, int by,
    const float* __restrict__ A, const float* __restrict__ B,
    const float* __restrict__ bias, float* __restrict__ C, int Nc)
{
    __shared__ float Asf[16][128];
    __shared__ float Bsf[16][64];

    const int bm  = by * 128;
    const int bn  = bx * 64;
    const int tid = threadIdx.x;
    const int tr  = tid >> 4;
    const int tc  = tid & 15;

    // A-tile mapping: thread loads row (tid>>1), k-cols [cb, cb+8)
    const int arow = tid >> 1;
    const int acb  = (tid & 1) * 8;
    // B-tile mapping: row tid>>4, 4 cols at (tid&15)*4
    const int brow = tid >> 4;
    const int bc4  = (tid & 15) << 2;

    unsigned long long acc2[4][4];
    #pragma unroll
    for (int i = 0; i < 4; i++)
        #pragma unroll
        for (int j = 0; j < 4; j++) acc2[i][j] = 0ULL;

    // prefetch chunk 0
    float4 ra0 = *(const float4*)&A[(size_t)(bm + arow) * 256 + acb];
    float4 ra1 = *(const float4*)&A[(size_t)(bm + arow) * 256 + acb + 4];
    float4 rb  = *(const float4*)&B[(size_t)brow * Nc + bn + bc4];

    for (int k0 = 0; k0 < 256; k0 += 16) {
        // store staged tiles (A transposed [k][row])
        Asf[acb + 0][arow] = ra0.x;
        Asf[acb + 1][arow] = ra0.y;
        Asf[acb + 2][arow] = ra0.z;
        Asf[acb + 3][arow] = ra0.w;
        Asf[acb + 4][arow] = ra1.x;
        Asf[acb + 5][arow] = ra1.y;
        Asf[acb + 6][arow] = ra1.z;
        Asf[acb + 7][arow] = ra1.w;
        *(float4*)&Bsf[brow][bc4] = rb;
        __syncthreads();

        // prefetch next chunk (overlaps with compute below)
        if (k0 + 16 < 256) {
            ra0 = *(const float4*)&A[(size_t)(bm + arow) * 256 + k0 + 16 + acb];
            ra1 = *(const float4*)&A[(size_t)(bm + arow) * 256 + k0 + 16 + acb + 4];
            rb  = *(const float4*)&B[(size_t)(k0 + 16 + brow) * Nc + bn + bc4];
        }

        #pragma unroll
        for (int k = 0; k < 16; k++) {
            unsigned long long aa[4], bb[4];
            #pragma unroll
            for (int i = 0; i < 4; i++) {
                float2 ap = *(const float2*)&Asf[k][tr * 8 + i * 2];
                aa[i] = pack2(ap.x, ap.y);
            }
            float4 bq = *(const float4*)&Bsf[k][tc * 4];   // one LDS.128
            bb[0] = pack_dup(bq.x);
            bb[1] = pack_dup(bq.y);
            bb[2] = pack_dup(bq.z);
            bb[3] = pack_dup(bq.w);
            #pragma unroll
            for (int i = 0; i < 4; i++)
                #pragma unroll
                for (int j = 0; j < 4; j++)
                    ffma2(acc2[i][j], aa[i], bb[j]);
        }
        __syncthreads();
    }

    const int colb = bn + tc * 4;
    float4 bv = *(const float4*)&bias[colb];
    #pragma unroll
    for (int i = 0; i < 4; i++) {
        int row0 = bm + tr * 8 + i * 2;
        float2 c0 = unpack2(acc2[i][0]);
        float2 c1 = unpack2(acc2[i][1]);
        float2 c2 = unpack2(acc2[i][2]);
        float2 c3 = unpack2(acc2[i][3]);
        float4 lo = make_float4(c0.x + bv.x, c1.x + bv.y, c2.x + bv.z, c3.x + bv.w);
        float4 hi = make_float4(c0.y + bv.x, c1.y + bv.y, c2.y + bv.z, c3.y + bv.w);
        *(float4*)&C[(size_t)row0 * Nc + colb]       = lo;
        *(float4*)&C[(size_t)(row0 + 1) * Nc + colb] = hi;
    }
}

// ===========================================================================
// Weight pre-rounding (tf32 RNA)
// ===========================================================================
__global__ void __launch_bounds__(256) roundW_kernel(
    const float* __restrict__ W_val, const float* __restrict__ W_out)
{
    int i = blockIdx.x * 256 + threadIdx.x;
    g_Wval_r[i] = __uint_as_float(f2tf32(W_val[i]));
    g_Wout_r[i] = __uint_as_float(f2tf32(W_out[i]));
}

// ===========================================================================
// Fused phase-1: heterogeneous CTAs
// ===========================================================================
__global__ void __launch_bounds__(256, 2) phase1_kernel(
    const float* __restrict__ value,   const float* __restrict__ b_val,
    const float* __restrict__ vmaskin, const float* __restrict__ queries,
    const float* __restrict__ W_attn,  const float* __restrict__ b_attn,
    const float* __restrict__ W_off,   const float* __restrict__ b_off)
{
    extern __shared__ char dyn[];
    int sid = (int)(((long long)blockIdx.x * 997) % N_TOT);
    if (sid < N_VM) {
        tf32_gemm_v2(dyn, sid & 1, sid >> 1, value, g_Wval_r, b_val, vmaskin,
                     g_vmask, 256);
    } else if (sid < N_VM + N_LG) {
        int t = sid - N_VM;
        sgemm_body(t & 1, t >> 1, queries, W_attn, b_attn, g_logits, 128);
    } else {
        int t = sid - N_VM - N_LG;
        sgemm_body(t & 3, t >> 2, queries, W_off, b_off, g_deltas, 256);
    }
}

// ===========================================================================
// Output projection: pipelined tf32 GEMM
// ===========================================================================
__global__ void __launch_bounds__(256, 2) outproj_kernel(
    const float* __restrict__ bias, float* __restrict__ out)
{
    extern __shared__ char dyn[];
    tf32_gemm_v2(dyn, blockIdx.x, blockIdx.y, g_mdv, g_Wout_r, bias, nullptr,
                 out, 256);
}

// ===========================================================================
// Sampling (LDG.128 per point, corner butterfly merge)
// ===========================================================================
__global__ void __launch_bounds__(256) sample_kernel(
    const float* __restrict__ geom)
{
    __shared__ int4   sI[8][16];
    __shared__ float4 sW[8][16];

    const int nq = blockIdx.x;
    const int n  = nq / SQ;
    const int t  = threadIdx.x;

    if (t < 128) {
        const int m = t >> 4;
        const int p = t & 15;

        float cx = 1.f / (1.f + __expf(-geom[nq * 4 + 0]));
        float cy = 1.f / (1.f + __expf(-geom[nq * 4 + 1]));
        float sw = 0.125f / (1.f + __expf(-geom[nq * 4 + 2]));
        float sh = 0.125f / (1.f + __expf(-geom[nq * 4 + 3]));

        float l = g_logits[(size_t)nq * 128 + m * 16 + p];
        float mx = l;
        #pragma unroll
        for (int d = 8; d >= 1; d >>= 1)
            mx = fmaxf(mx, __shfl_xor_sync(0xffffffffu, mx, d, 16));
        float e = __expf(l - mx);
        float s = e;
        #pragma unroll
        for (int d = 8; d >= 1; d >>= 1)
            s += __shfl_xor_sync(0xffffffffu, s, d, 16);
        const float a = e / s;

        const float dx = g_deltas[(size_t)nq * 256 + m * 32 + 2 * p];
        const float dy = g_deltas[(size_t)nq * 256 + m * 32 + 2 * p + 1];

        const int li = p >> 2;
        const int HW = 128 >> li;
        const int starts[4] = {0, 16384, 20480, 21504};
        const int start = starts[li];

        float px = fmaf(dx, sw, cx);
        float py = fmaf(dy, sh, cy);
        float gx = fminf(fmaxf(2.f * px - 1.f, -1.f), 1.f);
        float gy = fminf(fmaxf(2.f * py - 1.f, -1.f), 1.f);
        float x = (gx + 1.f) * (HW * 0.5f) - 0.5f;
        float y = (gy + 1.f) * (HW * 0.5f) - 0.5f;
        float x0f = floorf(x), y0f = floorf(y);
        float wx = x - x0f, wy = y - y0f;
        int x0 = (int)x0f, y0 = (int)y0f;
        int x1 = x0 + 1,  y1 = y0 + 1;

        bool vx0 = (x0 >= 0) & (x0 < HW);
        bool vx1 = (x1 >= 0) & (x1 < HW);
        bool vy0 = (y0 >= 0) & (y0 < HW);
        bool vy1 = (y1 >= 0) & (y1 < HW);

        int4 idx;
        float4 w;
        idx.x = (vx0 & vy0) ? (start + y0 * HW + x0) * 256 : 0;
        idx.y = (vx1 & vy0) ? (start + y0 * HW + x1) * 256 : 0;
        idx.z = (vx0 & vy1) ? (start + y1 * HW + x0) * 256 : 0;
        idx.w = (vx1 & vy1) ? (start + y1 * HW + x1) * 256 : 0;
        w.x = (vx0 & vy0) ? a * (1.f - wx) * (1.f - wy) : 0.f;
        w.y = (vx1 & vy0) ? a * wx * (1.f - wy)         : 0.f;
        w.z = (vx0 & vy1) ? a * (1.f - wx) * wy         : 0.f;
        w.w = (vx1 & vy1) ? a * wx * wy                 : 0.f;

        sI[m][p] = idx;
        sW[m][p] = w;
    }
    __syncthreads();

    const int m      = t >> 5;
    const int lane   = t & 31;
    const int corner = lane >> 3;
    const int cb     = lane & 7;
    const float* __restrict__ vb4 =
        g_vmask + (size_t)n * S_TOT * 256 + m * 32 + cb * 4;
    const int*   __restrict__ pI = (const int*)&sI[m][0]   + corner;
    const float* __restrict__ pW = (const float*)&sW[m][0] + corner;

    float4 acc = make_float4(0.f, 0.f, 0.f, 0.f);
    #pragma unroll
    for (int p = 0; p < 16; p++) {
        int   I = pI[4 * p];
        float w = pW[4 * p];
        float4 v = *(const float4*)(vb4 + I);
        acc.x = fmaf(w, v.x, acc.x);
        acc.y = fmaf(w, v.y, acc.y);
        acc.z = fmaf(w, v.z, acc.z);
        acc.w = fmaf(w, v.w, acc.w);
    }

    #pragma unroll
    for (int d = 8; d <= 16; d <<= 1) {
        acc.x += __shfl_xor_sync(0xffffffffu, acc.x, d);
        acc.y += __shfl_xor_sync(0xffffffffu, acc.y, d);
        acc.z += __shfl_xor_sync(0xffffffffu, acc.z, d);
        acc.w += __shfl_xor_sync(0xffffffffu, acc.w, d);
    }
    if (lane < 8)
        *(float4*)&g_mdv[(size_t)nq * 256 + m * 32 + cb * 4] = acc;
}

// ===========================================================================
// Launch (R13-proven serial structure)
// ===========================================================================
extern "C" void kernel_launch(void* const* d_in, const int* in_sizes, int n_in,
                              void* d_out, int out_size)
{
    const float* queries = (const float*)d_in[0];
    const float* geom    = (const float*)d_in[1];
    const float* value   = (const float*)d_in[2];
    const float* vmaskin = (const float*)d_in[3];
    const float* W_off   = (const float*)d_in[4];
    const float* b_off   = (const float*)d_in[5];
    const float* W_attn  = (const float*)d_in[6];
    const float* b_attn  = (const float*)d_in[7];
    const float* W_val   = (const float*)d_in[8];
    const float* b_val   = (const float*)d_in[9];
    const float* W_out   = (const float*)d_in[10];
    const float* b_out   = (const float*)d_in[11];
    float* out = (float*)d_out;

    static int attr_done = 0;
    if (!attr_done) {
        cudaFuncSetAttribute(phase1_kernel,
                             cudaFuncAttributeMaxDynamicSharedMemorySize,
                             TF32_DSMEM);
        cudaFuncSetAttribute(outproj_kernel,
                             cudaFuncAttributeMaxDynamicSharedMemorySize,
                             TF32_DSMEM);
        attr_done = 1;
    }

    // Pre-round weights (tf32 RNA) for the tensor-core B path
    roundW_kernel<<<256, 256>>>(W_val, W_out);
    // Phase 1 (fused): vmask tf32-MMA + logits/deltas exact fp32
    phase1_kernel<<<N_TOT, 256, TF32_DSMEM>>>(value, b_val, vmaskin,
                                              queries, W_attn, b_attn,
                                              W_off, b_off);
    // Phase 2: sampling -> g_mdv
    sample_kernel<<<NQ, 256>>>(geom);
    // Phase 3: out = mdv @ W_out + b_out (tf32 MMA, pipelined)
    outproj_kernel<<<dim3(2, NQ / 128), 256, TF32_DSMEM>>>(b_out, out);
}

// round 17
// speedup vs baseline: 1.2139x; 1.0705x over previous
#include <cuda_runtime.h>
#include <math.h>
#include <stdint.h>

#define SQ      8192
#define NBATCH  2
#define S_TOT   21760
#define NQ      (NBATCH*SQ)      // 16384
#define NS      (NBATCH*S_TOT)   // 43520

// Fused phase-1 grid: 680 fp16-vmask CTAs + 256 logits CTAs + 512 deltas CTAs
#define N_VM   680
#define N_LG   256
#define N_DL   512
#define N_TOT  1448

// fp16 GEMM smem geometry
// A buffer : [m(128)][kpair stride 12] uint32 = 6144 B (single-buffered)
// B stages : [kpair(8)][n stride 136] uint32  = 4352 B x 3
#define AP_STRIDE   12
#define BP_STRIDE   136
#define A_BYTES     (128*AP_STRIDE*4)            // 6144
#define B_STAGE     (8*BP_STRIDE*4)              // 4352
#define H16_DSMEM   (A_BYTES + 3*B_STAGE)        // 19200 < 48KB default

// Scratch (device globals: referenced ONLY inside device code)
__device__ float    g_vmask [(size_t)NS*256];
__device__ float    g_logits[(size_t)NQ*128];
__device__ float    g_deltas[(size_t)NQ*256];
__device__ float    g_mdv   [(size_t)NQ*256];
__device__ uint32_t g_Wval_h[128*256];   // half2 k-pair packed weights
__device__ uint32_t g_Wout_h[128*256];

// ===========================================================================
// PTX helpers
// ===========================================================================
__device__ __forceinline__ uint32_t pack_h2(float lo, float hi) {
    uint32_t r;   // d.lo = cvt(lo), d.hi = cvt(hi)
    asm("cvt.rn.f16x2.f32 %0, %1, %2;" : "=r"(r) : "f"(hi), "f"(lo));
    return r;
}
__device__ __forceinline__ void mma_f16_k16(float c[4],
                                            uint32_t a0, uint32_t a1,
                                            uint32_t a2, uint32_t a3,
                                            uint32_t b0, uint32_t b1) {
    asm volatile(
        "mma.sync.aligned.m16n8k16.row.col.f32.f16.f16.f32 "
        "{%0,%1,%2,%3}, {%4,%5,%6,%7}, {%8,%9}, {%0,%1,%2,%3};"
        : "+f"(c[0]), "+f"(c[1]), "+f"(c[2]), "+f"(c[3])
        : "r"(a0), "r"(a1), "r"(a2), "r"(a3), "r"(b0), "r"(b1));
}
__device__ __forceinline__ uint32_t smem_u32(const void* p) {
    uint32_t a;
    asm("{ .reg .u64 t; cvta.to.shared.u64 t, %1; cvt.u32.u64 %0, t; }"
        : "=r"(a) : "l"(p));
    return a;
}
__device__ __forceinline__ void cp_async16(uint32_t dst, const void* src) {
    asm volatile("cp.async.cg.shared.global [%0], [%1], 16;"
                 :: "r"(dst), "l"(src));
}
#define CP_COMMIT() asm volatile("cp.async.commit_group;" ::: "memory")
#define CP_WAIT1()  asm volatile("cp.async.wait_group 1;" ::: "memory")

// ===========================================================================
// fp16 tensor-core GEMM (m16n8k16):
//   C[.. x Nc] = (A[.. x 256] @ W[256 x Nc] + bias) (* rowscale)
// Wh: half2 k-pair packed weights [128][Nc] (prep kernel).
// A: fp32, converted to half2 pairs on the LDG->cvt->STS path.
// B: 3-stage cp.async pipeline; A: register double-buffered, single smem buf.
// 256 threads, warp tile 32x64 = 2 mf x 8 nf MMAs per K=16 chunk.
// ===========================================================================
__device__ void h16_gemm(
    char* dyn, int bx, int by,
    const float* __restrict__ A, const uint32_t* __restrict__ Wh,
    const float* __restrict__ bias, const float* __restrict__ rowscale,
    float* __restrict__ C, int Nc)
{
    const int tid  = threadIdx.x;
    const int wid  = tid >> 5;
    const int lane = tid & 31;
    const int m0   = (wid & 3) * 32;
    const int n0   = (wid >> 2) * 64;
    const int grp  = lane >> 2;
    const int q    = lane & 3;
    const int bm   = by * 128;
    const int bn   = bx * 128;

    const uint32_t sbase = smem_u32(dyn);

    float c[2][8][4];
    #pragma unroll
    for (int i = 0; i < 2; i++)
        #pragma unroll
        for (int j = 0; j < 8; j++)
            #pragma unroll
            for (int e = 0; e < 4; e++) c[i][j][e] = 0.f;

    // A staging mapping: row = tid>>1, k-cols [(tid&1)*8 .. +8)
    const int arow = tid >> 1;
    const int ak8  = (tid & 1) * 8;
    // B staging: kpair row = tid>>5 (0..7), 4 cols at (tid&31)*4
    const int bkr  = tid >> 5;
    const int bnc4 = (tid & 31) << 2;

    auto issueB = [&](int ck, int s) {
        uint32_t Bs = sbase + A_BYTES + (uint32_t)s * B_STAGE;
        cp_async16(Bs + (uint32_t)((bkr * BP_STRIDE + bnc4) * 4),
                   &Wh[(size_t)(ck * 8 + bkr) * Nc + bn + bnc4]);
    };

    issueB(0, 0); CP_COMMIT();
    issueB(1, 1); CP_COMMIT();

    // prefetch A chunk 0
    float4 ra0 = *(const float4*)&A[(size_t)(bm + arow) * 256 + ak8];
    float4 ra1 = *(const float4*)&A[(size_t)(bm + arow) * 256 + ak8 + 4];

    uint32_t* Am = (uint32_t*)dyn;           // [m][AP_STRIDE]

    for (int ck = 0; ck < 16; ck++) {
        // store A chunk ck as half2 k-pairs (one STS.128)
        {
            uint4 u;
            u.x = pack_h2(ra0.x, ra0.y);
            u.y = pack_h2(ra0.z, ra0.w);
            u.z = pack_h2(ra1.x, ra1.y);
            u.w = pack_h2(ra1.z, ra1.w);
            *(uint4*)&Am[arow * AP_STRIDE + (ak8 >> 1)] = u;
        }
        CP_WAIT1();                 // B(ck) complete
        __syncthreads();

        if (ck + 2 < 16) issueB(ck + 2, (ck + 2) % 3);
        CP_COMMIT();                // empty groups in tail are fine

        // prefetch A chunk ck+1 (overlaps compute)
        if (ck + 1 < 16) {
            ra0 = *(const float4*)&A[(size_t)(bm + arow) * 256 + (ck + 1) * 16 + ak8];
            ra1 = *(const float4*)&A[(size_t)(bm + arow) * 256 + (ck + 1) * 16 + ak8 + 4];
        }

        const uint32_t* Bkp =
            (const uint32_t*)(dyn + A_BYTES + (ck % 3) * B_STAGE);

        uint32_t a[2][4];
        #pragma unroll
        for (int mf = 0; mf < 2; mf++) {
            int mr = m0 + mf * 16 + grp;
            a[mf][0] = Am[mr * AP_STRIDE + q];
            a[mf][1] = Am[(mr + 8) * AP_STRIDE + q];
            a[mf][2] = Am[mr * AP_STRIDE + q + 4];
            a[mf][3] = Am[(mr + 8) * AP_STRIDE + q + 4];
        }
        uint32_t b[8][2];
        #pragma unroll
        for (int nf = 0; nf < 8; nf++) {
            int nb = n0 + nf * 8 + grp;
            b[nf][0] = Bkp[q * BP_STRIDE + nb];
            b[nf][1] = Bkp[(q + 4) * BP_STRIDE + nb];
        }
        #pragma unroll
        for (int mf = 0; mf < 2; mf++)
            #pragma unroll
            for (int nf = 0; nf < 8; nf++)
                mma_f16_k16(c[mf][nf], a[mf][0], a[mf][1], a[mf][2], a[mf][3],
                            b[nf][0], b[nf][1]);
        __syncthreads();
    }

    #pragma unroll
    for (int mf = 0; mf < 2; mf++) {
        int r0 = bm + m0 + mf * 16 + grp;
        int r1 = r0 + 8;
        float rs0 = rowscale ? rowscale[r0] : 1.f;
        float rs1 = rowscale ? rowscale[r1] : 1.f;
        #pragma unroll
        for (int nf = 0; nf < 8; nf++) {
            int col = bn + n0 + nf * 8 + 2 * q;
            float2 bv = *(const float2*)&bias[col];
            float2 lo = make_float2((c[mf][nf][0] + bv.x) * rs0,
                                    (c[mf][nf][1] + bv.y) * rs0);
            float2 hi = make_float2((c[mf][nf][2] + bv.x) * rs1,
                                    (c[mf][nf][3] + bv.y) * rs1);
            *(float2*)&C[(size_t)r0 * Nc + col] = lo;
            *(float2*)&C[(size_t)r1 * Nc + col] = hi;
        }
    }
}

// ===========================================================================
// f32x2 packed helpers (sgemm)
// ===========================================================================
__device__ __forceinline__ unsigned long long pack_dup(float v) {
    unsigned long long r;
    asm("mov.b64 %0, {%1, %1};" : "=l"(r) : "f"(v));
    return r;
}
__device__ __forceinline__ unsigned long long pack2(float lo, float hi) {
    unsigned long long r;
    asm("mov.b64 %0, {%1, %2};" : "=l"(r) : "f"(lo), "f"(hi));
    return r;
}
__device__ __forceinline__ float2 unpack2(unsigned long long v) {
    float2 r;
    asm("mov.b64 {%0, %1}, %2;" : "=f"(r.x), "=f"(r.y) : "l"(v));
    return r;
}
__device__ __forceinline__ void ffma2(unsigned long long& acc,
                                      unsigned long long a,
                                      unsigned long long b) {
    asm("fma.rn.f32x2 %0, %1, %2, %0;" : "+l"(acc) : "l"(a), "l"(b));
}

// ===========================================================================
// Exact fp32 SGEMM body (logits/deltas) — R16-proven version
// ===========================================================================
__device__ void sgemm_body(
    int bx, int by,
    const float* __restrict__ A, const float* __restrict__ B,
    const float* __restrict__ bias, float* __restrict__ C, int Nc)
{
    __shared__ float Asf[16][128];
    __shared__ float Bsf[16][64];

    const int bm  = by * 128;
    const int bn  = bx * 64;
    const int tid = threadIdx.x;
    const int tr  = tid >> 4;
    const int tc  = tid & 15;

    const int arow = tid >> 1;
    const int acb  = (tid & 1) * 8;
    const int brow = tid >> 4;
    const int bc4  = (tid & 15) << 2;

    unsigned long long acc2[4][4];
    #pragma unroll
    for (int i = 0; i < 4; i++)
        #pragma unroll
        for (int j = 0; j < 4; j++) acc2[i][j] = 0ULL;

    float4 ra0 = *(const float4*)&A[(size_t)(bm + arow) * 256 + acb];
    float4 ra1 = *(const float4*)&A[(size_t)(bm + arow) * 256 + acb + 4];
    float4 rb  = *(const float4*)&B[(size_t)brow * Nc + bn + bc4];

    for (int k0 = 0; k0 < 256; k0 += 16) {
        Asf[acb + 0][arow] = ra0.x;
        Asf[acb + 1][arow] = ra0.y;
        Asf[acb + 2][arow] = ra0.z;
        Asf[acb + 3][arow] = ra0.w;
        Asf[acb + 4][arow] = ra1.x;
        Asf[acb + 5][arow] = ra1.y;
        Asf[acb + 6][arow] = ra1.z;
        Asf[acb + 7][arow] = ra1.w;
        *(float4*)&Bsf[brow][bc4] = rb;
        __syncthreads();

        if (k0 + 16 < 256) {
            ra0 = *(const float4*)&A[(size_t)(bm + arow) * 256 + k0 + 16 + acb];
            ra1 = *(const float4*)&A[(size_t)(bm + arow) * 256 + k0 + 16 + acb + 4];
            rb  = *(const float4*)&B[(size_t)(k0 + 16 + brow) * Nc + bn + bc4];
        }

        #pragma unroll
        for (int k = 0; k < 16; k++) {
            unsigned long long aa[4], bb[4];
            #pragma unroll
            for (int i = 0; i < 4; i++) {
                float2 ap = *(const float2*)&Asf[k][tr * 8 + i * 2];
                aa[i] = pack2(ap.x, ap.y);
            }
            float4 bq = *(const float4*)&Bsf[k][tc * 4];
            bb[0] = pack_dup(bq.x);
            bb[1] = pack_dup(bq.y);
            bb[2] = pack_dup(bq.z);
            bb[3] = pack_dup(bq.w);
            #pragma unroll
            for (int i = 0; i < 4; i++)
                #pragma unroll
                for (int j = 0; j < 4; j++)
                    ffma2(acc2[i][j], aa[i], bb[j]);
        }
        __syncthreads();
    }

    const int colb = bn + tc * 4;
    float4 bv = *(const float4*)&bias[colb];
    #pragma unroll
    for (int i = 0; i < 4; i++) {
        int row0 = bm + tr * 8 + i * 2;
        float2 c0 = unpack2(acc2[i][0]);
        float2 c1 = unpack2(acc2[i][1]);
        float2 c2 = unpack2(acc2[i][2]);
        float2 c3 = unpack2(acc2[i][3]);
        float4 lo = make_float4(c0.x + bv.x, c1.x + bv.y, c2.x + bv.z, c3.x + bv.w);
        float4 hi = make_float4(c0.y + bv.x, c1.y + bv.y, c2.y + bv.z, c3.y + bv.w);
        *(float4*)&C[(size_t)row0 * Nc + colb]       = lo;
        *(float4*)&C[(size_t)(row0 + 1) * Nc + colb] = hi;
    }
}

// ===========================================================================
// Weight prep: fp16 RN conversion + half2 k-pair packing.
// g_W_h[kp][n] = {h(W[2kp][n]) lo, h(W[2kp+1][n]) hi}
// ===========================================================================
__global__ void __launch_bounds__(256) packW_kernel(
    const float* __restrict__ W_val, const float* __restrict__ W_out)
{
    int i = blockIdx.x * 256 + threadIdx.x;      // 0..32767
    int kp = i >> 8, n = i & 255;
    g_Wval_h[i] = pack_h2(W_val[(2 * kp) * 256 + n],
                          W_val[(2 * kp + 1) * 256 + n]);
    g_Wout_h[i] = pack_h2(W_out[(2 * kp) * 256 + n],
                          W_out[(2 * kp + 1) * 256 + n]);
}

// ===========================================================================
// Fused phase-1: heterogeneous CTAs
// ===========================================================================
__global__ void __launch_bounds__(256, 2) phase1_kernel(
    const float* __restrict__ value,   const float* __restrict__ b_val,
    const float* __restrict__ vmaskin, const float* __restrict__ queries,
    const float* __restrict__ W_attn,  const float* __restrict__ b_attn,
    const float* __restrict__ W_off,   const float* __restrict__ b_off)
{
    extern __shared__ char dyn[];
    int sid = (int)(((long long)blockIdx.x * 997) % N_TOT);
    if (sid < N_VM) {
        h16_gemm(dyn, sid & 1, sid >> 1, value, g_Wval_h, b_val, vmaskin,
                 g_vmask, 256);
    } else if (sid < N_VM + N_LG) {
        int t = sid - N_VM;
        sgemm_body(t & 1, t >> 1, queries, W_attn, b_attn, g_logits, 128);
    } else {
        int t = sid - N_VM - N_LG;
        sgemm_body(t & 3, t >> 2, queries, W_off, b_off, g_deltas, 256);
    }
}

// ===========================================================================
// Output projection (fp16 MMA)
// ===========================================================================
__global__ void __launch_bounds__(256, 2) outproj_kernel(
    const float* __restrict__ bias, float* __restrict__ out)
{
    extern __shared__ char dyn[];
    h16_gemm(dyn, blockIdx.x, blockIdx.y, g_mdv, g_Wout_h, bias, nullptr,
             out, 256);
}

// ===========================================================================
// Sampling (LDG.128 per point, corner butterfly merge) — R13/R16 proven
// ===========================================================================
__global__ void __launch_bounds__(256) sample_kernel(
    const float* __restrict__ geom)
{
    __shared__ int4   sI[8][16];
    __shared__ float4 sW[8][16];

    const int nq = blockIdx.x;
    const int n  = nq / SQ;
    const int t  = threadIdx.x;

    if (t < 128) {
        const int m = t >> 4;
        const int p = t & 15;

        float cx = 1.f / (1.f + __expf(-geom[nq * 4 + 0]));
        float cy = 1.f / (1.f + __expf(-geom[nq * 4 + 1]));
        float sw = 0.125f / (1.f + __expf(-geom[nq * 4 + 2]));
        float sh = 0.125f / (1.f + __expf(-geom[nq * 4 + 3]));

        float l = g_logits[(size_t)nq * 128 + m * 16 + p];
        float mx = l;
        #pragma unroll
        for (int d = 8; d >= 1; d >>= 1)
            mx = fmaxf(mx, __shfl_xor_sync(0xffffffffu, mx, d, 16));
        float e = __expf(l - mx);
        float s = e;
        #pragma unroll
        for (int d = 8; d >= 1; d >>= 1)
            s += __shfl_xor_sync(0xffffffffu, s, d, 16);
        const float a = e / s;

        const float dx = g_deltas[(size_t)nq * 256 + m * 32 + 2 * p];
        const float dy = g_deltas[(size_t)nq * 256 + m * 32 + 2 * p + 1];

        const int li = p >> 2;
        const int HW = 128 >> li;
        const int starts[4] = {0, 16384, 20480, 21504};
        const int start = starts[li];

        float px = fmaf(dx, sw, cx);
        float py = fmaf(dy, sh, cy);
        float gx = fminf(fmaxf(2.f * px - 1.f, -1.f), 1.f);
        float gy = fminf(fmaxf(2.f * py - 1.f, -1.f), 1.f);
        float x = (gx + 1.f) * (HW * 0.5f) - 0.5f;
        float y = (gy + 1.f) * (HW * 0.5f) - 0.5f;
        float x0f = floorf(x), y0f = floorf(y);
        float wx = x - x0f, wy = y - y0f;
        int x0 = (int)x0f, y0 = (int)y0f;
        int x1 = x0 + 1,  y1 = y0 + 1;

        bool vx0 = (x0 >= 0) & (x0 < HW);
        bool vx1 = (x1 >= 0) & (x1 < HW);
        bool vy0 = (y0 >= 0) & (y0 < HW);
        bool vy1 = (y1 >= 0) & (y1 < HW);

        int4 idx;
        float4 w;
        idx.x = (vx0 & vy0) ? (start + y0 * HW + x0) * 256 : 0;
        idx.y = (vx1 & vy0) ? (start + y0 * HW + x1) * 256 : 0;
        idx.z = (vx0 & vy1) ? (start + y1 * HW + x0) * 256 : 0;
        idx.w = (vx1 & vy1) ? (start + y1 * HW + x1) * 256 : 0;
        w.x = (vx0 & vy0) ? a * (1.f - wx) * (1.f - wy) : 0.f;
        w.y = (vx1 & vy0) ? a * wx * (1.f - wy)         : 0.f;
        w.z = (vx0 & vy1) ? a * (1.f - wx) * wy         : 0.f;
        w.w = (vx1 & vy1) ? a * wx * wy                 : 0.f;

        sI[m][p] = idx;
        sW[m][p] = w;
    }
    __syncthreads();

    const int m      = t >> 5;
    const int lane   = t & 31;
    const int corner = lane >> 3;
    const int cb     = lane & 7;
    const float* __restrict__ vb4 =
        g_vmask + (size_t)n * S_TOT * 256 + m * 32 + cb * 4;
    const int*   __restrict__ pI = (const int*)&sI[m][0]   + corner;
    const float* __restrict__ pW = (const float*)&sW[m][0] + corner;

    float4 acc = make_float4(0.f, 0.f, 0.f, 0.f);
    #pragma unroll
    for (int p = 0; p < 16; p++) {
        int   I = pI[4 * p];
        float w = pW[4 * p];
        float4 v = *(const float4*)(vb4 + I);
        acc.x = fmaf(w, v.x, acc.x);
        acc.y = fmaf(w, v.y, acc.y);
        acc.z = fmaf(w, v.z, acc.z);
        acc.w = fmaf(w, v.w, acc.w);
    }

    #pragma unroll
    for (int d = 8; d <= 16; d <<= 1) {
        acc.x += __shfl_xor_sync(0xffffffffu, acc.x, d);
        acc.y += __shfl_xor_sync(0xffffffffu, acc.y, d);
        acc.z += __shfl_xor_sync(0xffffffffu, acc.z, d);
        acc.w += __shfl_xor_sync(0xffffffffu, acc.w, d);
    }
    if (lane < 8)
        *(float4*)&g_mdv[(size_t)nq * 256 + m * 32 + cb * 4] = acc;
}

// ===========================================================================
// Launch (serial; dyn smem < 48KB so no attributes, no statics)
// ===========================================================================
extern "C" void kernel_launch(void* const* d_in, const int* in_sizes, int n_in,
                              void* d_out, int out_size)
{
    const float* queries = (const float*)d_in[0];
    const float* geom    = (const float*)d_in[1];
    const float* value   = (const float*)d_in[2];
    const float* vmaskin = (const float*)d_in[3];
    const float* W_off   = (const float*)d_in[4];
    const float* b_off   = (const float*)d_in[5];
    const float* W_attn  = (const float*)d_in[6];
    const float* b_attn  = (const float*)d_in[7];
    const float* W_val   = (const float*)d_in[8];
    const float* b_val   = (const float*)d_in[9];
    const float* W_out   = (const float*)d_in[10];
    const float* b_out   = (const float*)d_in[11];
    float* out = (float*)d_out;

    // Weight prep: fp16 RN + half2 k-pair packing
    packW_kernel<<<128, 256>>>(W_val, W_out);
    // Phase 1 (fused): vmask fp16-MMA + logits/deltas exact fp32
    phase1_kernel<<<N_TOT, 256, H16_DSMEM>>>(value, b_val, vmaskin,
                                             queries, W_attn, b_attn,
                                             W_off, b_off);
    // Phase 2: sampling -> g_mdv
    sample_kernel<<<NQ, 256>>>(geom);
    // Phase 3: out = mdv @ W_out + b_out (fp16 MMA)
    outproj_kernel<<<dim3(2, NQ / 128), 256, H16_DSMEM>>>(b_out, out);
}